// round 14
// baseline (speedup 1.0000x reference)
#include <cuda_runtime.h>
#include <cuda_bf16.h>
#include <cstddef>
#include <cstdint>

// ---------------- problem constants ----------------
#define NN 20000
#define EE 240000
#define GG 128
#define F_IN 128
#define EMB 256
#define HH 2
#define HC 512          // H*EMB
#define DENSE 512
#define NCLS 10

// ---------------- scratch (device globals; no allocation) ----------------
#define OFF_H     0                         // [N,512]
#define OFF_GAT   (OFF_H   + NN*512)        // [N,512]
#define OFF_X     (OFF_GAT + NN*512)        // [N,256]
#define OFF_ALS   (OFF_X   + NN*256)        // [N,2]
#define OFF_ALD   (OFF_ALS + NN*2)          // [N,2]
#define OFF_POOL  (OFF_ALD + NN*2)          // [G,512] accumulated reps
#define OFF_DENSE (OFF_POOL + GG*512)       // [G,512]
#define FBUF_SZ   (OFF_DENSE + GG*512)

__device__ float g_fbuf[FBUF_SZ];

#define IOFF_DEG    0
#define IOFF_ROWS   (IOFF_DEG + NN)         // N+1
#define IOFF_WP     (IOFF_ROWS + NN + 1)    // N+1
#define IOFF_CSR    (IOFF_WP + NN + 1)      // E+N
#define IOFF_GSTART (IOFF_CSR + EE + NN)    // G+1
#define IBUF_SZ     (IOFF_GSTART + GG + 1)

__device__ int g_ibuf[IBUF_SZ];

// ---------------- init: deg=1 (self loop), zero pooled accumulator ----------------
__global__ void k_init(int* deg, float* pool) {
    int i = blockIdx.x * blockDim.x + threadIdx.x;
    if (i < NN) deg[i] = 1;
    if (i < GG * 512) pool[i] = 0.f;
}

// count in-degrees of real edges
__global__ void k_count(const int* __restrict__ ei, int* deg) {
    int e = blockIdx.x * blockDim.x + threadIdx.x;
    if (e < EE) atomicAdd(&deg[ei[EE + e]], 1);
}

// exclusive scan of deg[0..N) -> rows[0..N] AND wp[0..N], single block of 1024
#define SCAN_T 1024
__global__ void k_scan(const int* __restrict__ deg, int* rows, int* wp) {
    __shared__ int sh[SCAN_T];
    int tid = threadIdx.x;
    const int items = (NN + SCAN_T - 1) / SCAN_T;
    int start = tid * items;
    int local = 0;
    for (int i = 0; i < items; i++) {
        int idx = start + i;
        if (idx < NN) local += deg[idx];
    }
    sh[tid] = local;
    __syncthreads();
    for (int d = 1; d < SCAN_T; d <<= 1) {
        int v = (tid >= d) ? sh[tid - d] : 0;
        __syncthreads();
        sh[tid] += v;
        __syncthreads();
    }
    int run = sh[tid] - local;  // exclusive offset
    for (int i = 0; i < items; i++) {
        int idx = start + i;
        if (idx < NN) { rows[idx] = run; wp[idx] = run; run += deg[idx]; }
    }
    if (tid == SCAN_T - 1) { rows[NN] = sh[SCAN_T - 1]; wp[NN] = sh[SCAN_T - 1]; }
}

// scatter edges (and self loops) into CSR-by-dst
__global__ void k_scatter(const int* __restrict__ ei, int* wp, int* csr) {
    int i = blockIdx.x * blockDim.x + threadIdx.x;
    if (i >= EE + NN) return;
    int s, d;
    if (i < EE) { s = ei[i]; d = ei[EE + i]; }
    else        { s = d = i - EE; }
    int pos = atomicAdd(&wp[d], 1);
    csr[pos] = s;
}

// graph boundaries from sorted batch_index
__global__ void k_gstart(const int* __restrict__ batch, int* gstart) {
    int v = blockIdx.x * blockDim.x + threadIdx.x;
    if (v >= NN) return;
    int b = batch[v];
    if (v == 0) {
        for (int g = 0; g <= b; g++) gstart[g] = 0;
    } else {
        int bp = batch[v - 1];
        for (int g = bp + 1; g <= b; g++) gstart[g] = v;
    }
    if (v == NN - 1) {
        for (int g = b + 1; g <= GG; g++) gstart[g] = NN;
    }
}

// ---------------- tf32 tensor-core GEMM, double-buffered, STATIC smem ------
// C[M,Nc] = A[M,K] * B[K,Nc] (+bias)(+relu), fp32 accumulate.
// CTA tile 128x128, K-chunk 16; 8 warps (2M x 4N), warp tile 64x32 = 4x4 m16n8k8.
// Static smem: 2 stages x (A 128x20 + B 16x132) words = 37376 B (< 48 KB).
// Pipeline: prefetch chunk c+1 into registers during compute of chunk c,
// STS into the alternate stage, single __syncthreads per chunk.

__device__ __forceinline__ uint32_t f2tf32(float f) {
    uint32_t r;
    asm("cvt.rna.tf32.f32 %0, %1;" : "=r"(r) : "f"(f));
    return r;
}

#define MMA_TF32(c, a, b) \
    asm("mma.sync.aligned.m16n8k8.row.col.f32.tf32.tf32.f32 " \
        "{%0,%1,%2,%3}, {%4,%5,%6,%7}, {%8,%9}, {%0,%1,%2,%3};" \
        : "+f"((c)[0]), "+f"((c)[1]), "+f"((c)[2]), "+f"((c)[3]) \
        : "r"((a)[0]), "r"((a)[1]), "r"((a)[2]), "r"((a)[3]), \
          "r"((b)[0]), "r"((b)[1]))

#define AS_STRIDE 20                          // 16 cols + pad
#define BS_STRIDE 132                         // 128 cols + pad
#define A_WORDS   (128 * AS_STRIDE)           // 2560
#define B_WORDS   (16 * BS_STRIDE)            // 2112
#define STAGE_SZ  (A_WORDS + B_WORDS)         // 4672 words = 18688 B

__global__ __launch_bounds__(256) void k_mma(
    const float* __restrict__ A, const float* __restrict__ B,
    const float* __restrict__ bias, float* __restrict__ C,
    int M, int K, int Nc, int doRelu)
{
    __shared__ uint32_t smem_st[2 * STAGE_SZ];   // 37376 B static

    int tid = threadIdx.x;
    int wid = tid >> 5, lane = tid & 31;
    int wm = (wid >> 2) * 64;       // 0 or 64
    int wn = (wid & 3) * 32;        // 0,32,64,96
    int gid = lane >> 2, tig = lane & 3;
    int rowBase = blockIdx.y * 128;
    int colBase = blockIdx.x * 128;

    // per-thread load coordinates (chunk = 16 K-cols)
    int a_r = tid >> 2, a_c = (tid & 3) * 4;       // rows a_r, a_r+64
    int b_r = tid >> 5, b_c = (tid & 31) * 4;      // rows b_r, b_r+8

    float c[4][4][4];
#pragma unroll
    for (int mt = 0; mt < 4; mt++)
#pragma unroll
        for (int nt = 0; nt < 4; nt++)
#pragma unroll
            for (int r = 0; r < 4; r++) c[mt][nt][r] = 0.f;

    float4 ra[2], rb[2];
    // ---- load chunk 0 into regs ----
#pragma unroll
    for (int i = 0; i < 2; i++) {
        int gr = rowBase + a_r + i * 64;
        ra[i] = (gr < M) ? *(const float4*)(A + (size_t)gr * K + a_c)
                         : make_float4(0.f, 0.f, 0.f, 0.f);
        rb[i] = *(const float4*)(B + (size_t)(b_r + i * 8) * Nc + colBase + b_c);
    }
    // ---- store chunk 0 into stage 0 ----
    {
        uint32_t* AsU = smem_st;
        uint32_t* BsU = smem_st + A_WORDS;
#pragma unroll
        for (int i = 0; i < 2; i++) {
            uint32_t* da = &AsU[(a_r + i * 64) * AS_STRIDE + a_c];
            da[0] = f2tf32(ra[i].x); da[1] = f2tf32(ra[i].y);
            da[2] = f2tf32(ra[i].z); da[3] = f2tf32(ra[i].w);
            uint32_t* db = &BsU[(b_r + i * 8) * BS_STRIDE + b_c];
            db[0] = f2tf32(rb[i].x); db[1] = f2tf32(rb[i].y);
            db[2] = f2tf32(rb[i].z); db[3] = f2tf32(rb[i].w);
        }
    }
    __syncthreads();

    int nchunks = K >> 4;
    for (int ch = 0; ch < nchunks; ch++) {
        int cur = ch & 1;
        uint32_t* AsU = smem_st + cur * STAGE_SZ;
        uint32_t* BsU = AsU + A_WORDS;
        bool havenext = (ch + 1 < nchunks);
        // prefetch next chunk (LDGs issued before compute; consumed at STS below)
        if (havenext) {
            int k0 = (ch + 1) << 4;
#pragma unroll
            for (int i = 0; i < 2; i++) {
                int gr = rowBase + a_r + i * 64;
                ra[i] = (gr < M) ? *(const float4*)(A + (size_t)gr * K + k0 + a_c)
                                 : make_float4(0.f, 0.f, 0.f, 0.f);
                rb[i] = *(const float4*)(B + (size_t)(k0 + b_r + i * 8) * Nc + colBase + b_c);
            }
        }
        // ---- compute from stage cur: 2 k8-steps ----
#pragma unroll
        for (int ks = 0; ks < 2; ks++) {
            uint32_t a[4][4], b[4][2];
#pragma unroll
            for (int mt = 0; mt < 4; mt++) {
                int r0 = wm + mt * 16 + gid;
                a[mt][0] = AsU[(r0)     * AS_STRIDE + ks * 8 + tig];
                a[mt][1] = AsU[(r0 + 8) * AS_STRIDE + ks * 8 + tig];
                a[mt][2] = AsU[(r0)     * AS_STRIDE + ks * 8 + tig + 4];
                a[mt][3] = AsU[(r0 + 8) * AS_STRIDE + ks * 8 + tig + 4];
            }
#pragma unroll
            for (int nt = 0; nt < 4; nt++) {
                int cc = wn + nt * 8 + gid;
                b[nt][0] = BsU[(ks * 8 + tig)     * BS_STRIDE + cc];
                b[nt][1] = BsU[(ks * 8 + tig + 4) * BS_STRIDE + cc];
            }
#pragma unroll
            for (int mt = 0; mt < 4; mt++)
#pragma unroll
                for (int nt = 0; nt < 4; nt++)
                    MMA_TF32(c[mt][nt], a[mt], b[nt]);
        }
        // ---- stage next chunk into alternate buffer ----
        if (havenext) {
            uint32_t* AsN = smem_st + (cur ^ 1) * STAGE_SZ;
            uint32_t* BsN = AsN + A_WORDS;
#pragma unroll
            for (int i = 0; i < 2; i++) {
                uint32_t* da = &AsN[(a_r + i * 64) * AS_STRIDE + a_c];
                da[0] = f2tf32(ra[i].x); da[1] = f2tf32(ra[i].y);
                da[2] = f2tf32(ra[i].z); da[3] = f2tf32(ra[i].w);
                uint32_t* db = &BsN[(b_r + i * 8) * BS_STRIDE + b_c];
                db[0] = f2tf32(rb[i].x); db[1] = f2tf32(rb[i].y);
                db[2] = f2tf32(rb[i].z); db[3] = f2tf32(rb[i].w);
            }
        }
        __syncthreads();
    }

    // ---- epilogue ----
#pragma unroll
    for (int mt = 0; mt < 4; mt++) {
        int r0 = rowBase + wm + mt * 16 + gid;
        int r1 = r0 + 8;
#pragma unroll
        for (int nt = 0; nt < 4; nt++) {
            int cc = colBase + wn + nt * 8 + 2 * tig;
            float2 v0 = make_float2(c[mt][nt][0], c[mt][nt][1]);
            float2 v1 = make_float2(c[mt][nt][2], c[mt][nt][3]);
            if (bias) {
                float b0 = bias[cc], b1 = bias[cc + 1];
                v0.x += b0; v0.y += b1; v1.x += b0; v1.y += b1;
            }
            if (doRelu) {
                v0.x = fmaxf(v0.x, 0.f); v0.y = fmaxf(v0.y, 0.f);
                v1.x = fmaxf(v1.x, 0.f); v1.y = fmaxf(v1.y, 0.f);
            }
            if (r0 < M) *(float2*)(C + (size_t)r0 * Nc + cc) = v0;
            if (r1 < M) *(float2*)(C + (size_t)r1 * Nc + cc) = v1;
        }
    }
}

// ---------------- per-node attention logit terms ----------------
__global__ void k_al(const float* __restrict__ h, const float* __restrict__ asrc,
                     const float* __restrict__ adst, float* __restrict__ als,
                     float* __restrict__ ald)
{
    int warp = (blockIdx.x * blockDim.x + threadIdx.x) >> 5;
    int lane = threadIdx.x & 31;
    if (warp >= NN) return;
    const float* hr = h + (size_t)warp * 512;
    float s0 = 0.f, s1 = 0.f, d0 = 0.f, d1 = 0.f;
#pragma unroll
    for (int i = 0; i < 8; i++) {
        int c = i * 32 + lane;
        float h0 = hr[c], h1 = hr[256 + c];
        s0 += h0 * asrc[c];        d0 += h0 * adst[c];
        s1 += h1 * asrc[256 + c];  d1 += h1 * adst[256 + c];
    }
#pragma unroll
    for (int off = 16; off; off >>= 1) {
        s0 += __shfl_xor_sync(0xffffffffu, s0, off);
        s1 += __shfl_xor_sync(0xffffffffu, s1, off);
        d0 += __shfl_xor_sync(0xffffffffu, d0, off);
        d1 += __shfl_xor_sync(0xffffffffu, d1, off);
    }
    if (lane == 0) {
        als[warp * 2] = s0; als[warp * 2 + 1] = s1;
        ald[warp * 2] = d0; ald[warp * 2 + 1] = d1;
    }
}

// ---------------- attention softmax + aggregation (one warp per dst node) -----------
__global__ void k_attn(const float* __restrict__ h, const float* __restrict__ als,
                       const float* __restrict__ ald, const float* __restrict__ bvec,
                       const int* __restrict__ rows, const int* __restrict__ csr,
                       float* __restrict__ out)
{
    int warp = (blockIdx.x * blockDim.x + threadIdx.x) >> 5;
    int lane = threadIdx.x & 31;
    if (warp >= NN) return;
    int v = warp;
    int s0 = rows[v], s1 = rows[v + 1];
    int deg = s1 - s0;
    float ad0 = ald[v * 2], ad1 = ald[v * 2 + 1];

    // pass 1: max logit per head
    float m0 = -1e30f, m1 = -1e30f;
    for (int base = 0; base < deg; base += 32) {
        int j = base + lane;
        if (j < deg) {
            int s = csr[s0 + j];
            float t0 = als[s * 2] + ad0;     t0 = fmaxf(t0, 0.2f * t0);
            float t1 = als[s * 2 + 1] + ad1; t1 = fmaxf(t1, 0.2f * t1);
            m0 = fmaxf(m0, t0); m1 = fmaxf(m1, t1);
        }
    }
#pragma unroll
    for (int off = 16; off; off >>= 1) {
        m0 = fmaxf(m0, __shfl_xor_sync(0xffffffffu, m0, off));
        m1 = fmaxf(m1, __shfl_xor_sync(0xffffffffu, m1, off));
    }

    // pass 2: exp weights + weighted aggregation, 2 edges/iter for load MLP
    float acc[16];
#pragma unroll
    for (int k = 0; k < 16; k++) acc[k] = 0.f;
    float den0 = 0.f, den1 = 0.f;
    int j = 0;
    for (; j + 2 <= deg; j += 2) {
        int sa = csr[s0 + j];
        int sb = csr[s0 + j + 1];
        float ta0 = als[sa * 2] + ad0;     ta0 = fmaxf(ta0, 0.2f * ta0);
        float ta1 = als[sa * 2 + 1] + ad1; ta1 = fmaxf(ta1, 0.2f * ta1);
        float tb0 = als[sb * 2] + ad0;     tb0 = fmaxf(tb0, 0.2f * tb0);
        float tb1 = als[sb * 2 + 1] + ad1; tb1 = fmaxf(tb1, 0.2f * tb1);
        float wa0 = __expf(ta0 - m0), wa1 = __expf(ta1 - m1);
        float wb0 = __expf(tb0 - m0), wb1 = __expf(tb1 - m1);
        den0 += wa0 + wb0; den1 += wa1 + wb1;
        const float* ha = h + (size_t)sa * 512 + lane;
        const float* hb = h + (size_t)sb * 512 + lane;
#pragma unroll
        for (int k = 0; k < 16; k++) {
            float va = ha[k * 32];
            float vb = hb[k * 32];
            acc[k] += (k < 8 ? wa0 : wa1) * va + (k < 8 ? wb0 : wb1) * vb;
        }
    }
    for (; j < deg; j++) {
        int s = csr[s0 + j];
        float t0 = als[s * 2] + ad0;     t0 = fmaxf(t0, 0.2f * t0);
        float t1 = als[s * 2 + 1] + ad1; t1 = fmaxf(t1, 0.2f * t1);
        float w0 = __expf(t0 - m0), w1 = __expf(t1 - m1);
        den0 += w0; den1 += w1;
        const float* hr = h + (size_t)s * 512 + lane;
#pragma unroll
        for (int k = 0; k < 16; k++)
            acc[k] += (k < 8 ? w0 : w1) * hr[k * 32];
    }
    float r0 = 1.0f / den0, r1 = 1.0f / den1;
    float* orow = out + (size_t)v * 512 + lane;
#pragma unroll
    for (int k = 0; k < 16; k++) {
        float val = acc[k] * (k < 8 ? r0 : r1) + bvec[k * 32 + lane];
        orow[k * 32] = fmaxf(val, 0.f);   // fused relu (post-GAT)
    }
}

// ---------------- pooling: per-graph max + mean, accumulated across layers ----------
__global__ void k_pool(const float* __restrict__ x, const int* __restrict__ gstart,
                       float* __restrict__ gacc)
{
    int g = blockIdx.x;
    int c = threadIdx.x;   // 256
    int s = gstart[g], e = gstart[g + 1];
    float mx = 0.f, sm = 0.f;   // post-relu values are >= 0
    int v = s;
    for (; v + 2 <= e; v += 2) {
        float a = x[(size_t)v * 256 + c];
        float b = x[(size_t)(v + 1) * 256 + c];
        sm += a + b; mx = fmaxf(mx, fmaxf(a, b));
    }
    if (v < e) {
        float a = x[(size_t)v * 256 + c];
        sm += a; mx = fmaxf(mx, a);
    }
    int cnt = e - s;
    float mean = (cnt > 0) ? sm / (float)cnt : 0.f;
    gacc[g * 512 + c]       += mx;
    gacc[g * 512 + 256 + c] += mean;
}

// ---------------- final tiny linear: [G,512] @ [512,10] + b ----------------
__global__ void k_line2(const float* __restrict__ gd, const float* __restrict__ W,
                        const float* __restrict__ b, float* __restrict__ out)
{
    __shared__ float sh[512];
    int g = blockIdx.x;
    for (int i = threadIdx.x; i < 512; i += blockDim.x) sh[i] = gd[g * 512 + i];
    __syncthreads();
    if (threadIdx.x < NCLS) {
        float acc = b[threadIdx.x];
        for (int k = 0; k < 512; k++) acc += sh[k] * W[k * NCLS + threadIdx.x];
        out[g * NCLS + threadIdx.x] = acc;
    }
}

// ---------------- host orchestration ----------------
extern "C" void kernel_launch(void* const* d_in, const int* in_sizes, int n_in,
                              void* d_out, int out_size)
{
    const float* x_in  = (const float*)d_in[0];
    const int*   ei    = (const int*)d_in[1];
    const int*   batch = (const int*)d_in[2];
    const float* attW[3]  = {(const float*)d_in[3],  (const float*)d_in[9],  (const float*)d_in[15]};
    const float* asrc[3]  = {(const float*)d_in[4],  (const float*)d_in[10], (const float*)d_in[16]};
    const float* adst[3]  = {(const float*)d_in[5],  (const float*)d_in[11], (const float*)d_in[17]};
    const float* attb[3]  = {(const float*)d_in[6],  (const float*)d_in[12], (const float*)d_in[18]};
    const float* linW[3]  = {(const float*)d_in[7],  (const float*)d_in[13], (const float*)d_in[19]};
    const float* linb[3]  = {(const float*)d_in[8],  (const float*)d_in[14], (const float*)d_in[20]};
    const float* line1W = (const float*)d_in[21];
    const float* line1b = (const float*)d_in[22];
    const float* line2W = (const float*)d_in[23];
    const float* line2b = (const float*)d_in[24];
    float* out = (float*)d_out;

    static float* fbuf = nullptr;
    static int*   ibuf = nullptr;
    if (!fbuf) {
        cudaGetSymbolAddress((void**)&fbuf, g_fbuf);
        cudaGetSymbolAddress((void**)&ibuf, g_ibuf);
    }

    float* bh    = fbuf + OFF_H;
    float* bgat  = fbuf + OFF_GAT;
    float* bx    = fbuf + OFF_X;
    float* bals  = fbuf + OFF_ALS;
    float* bald  = fbuf + OFF_ALD;
    float* bpool = fbuf + OFF_POOL;
    float* bdense= fbuf + OFF_DENSE;
    int* deg    = ibuf + IOFF_DEG;
    int* rows   = ibuf + IOFF_ROWS;
    int* wp     = ibuf + IOFF_WP;
    int* csr    = ibuf + IOFF_CSR;
    int* gstart = ibuf + IOFF_GSTART;

    int mtiles = (NN + 127) / 128;

    // ---- preprocessing part 1 (launch idx 0..2) ----
    {
        int n = GG * 512;  // >= NN
        k_init<<<(n + 255) / 256, 256>>>(deg, bpool);
        k_count<<<(EE + 255) / 256, 256>>>(ei, deg);
        k_scan<<<1, SCAN_T>>>(deg, rows, wp);
    }

    // ---- layer-1 h GEMM at launch idx 3 (profiled slot; independent of CSR) ----
    {
        dim3 grid(HC / 128, mtiles);
        k_mma<<<grid, 256>>>(x_in, attW[0], nullptr, bh, NN, F_IN, HC, 0);
    }

    // ---- preprocessing part 2 ----
    k_scatter<<<(EE + NN + 255) / 256, 256>>>(ei, wp, csr);
    k_gstart<<<(NN + 255) / 256, 256>>>(batch, gstart);

    // ---- three GAT layers ----
    const float* xcur = x_in;
    int fin = F_IN;
    for (int i = 0; i < 3; i++) {
        // h = x @ W (layer 0 already launched above)
        if (i > 0) {
            dim3 grid(HC / 128, mtiles);
            k_mma<<<grid, 256>>>(xcur, attW[i], nullptr, bh, NN, fin, HC, 0);
        }
        // per-node attention terms
        k_al<<<(NN * 32 + 255) / 256, 256>>>(bh, asrc[i], adst[i], bals, bald);
        // softmax-attention aggregation (+ bias + relu)
        k_attn<<<(NN * 32 + 255) / 256, 256>>>(bh, bals, bald, attb[i], rows, csr, bgat);
        // x = relu(gat @ lin_W + lin_b)   [N,512] x [512,256]
        {
            dim3 grid(EMB / 128, mtiles);
            k_mma<<<grid, 256>>>(bgat, linW[i], linb[i], bx, NN, HC, EMB, 1);
        }
        // pooling accumulation
        k_pool<<<GG, 256>>>(bx, gstart, bpool);
        xcur = bx;
        fin = EMB;
    }

    // ---- MLP head ----
    {
        dim3 grid(DENSE / 128, 1);
        k_mma<<<grid, 256>>>(bpool, line1W, line1b, bdense, GG, 2 * EMB, DENSE, 1);
    }
    k_line2<<<GG, 512>>>(bdense, line2W, line2b, out);
}

// round 16
// speedup vs baseline: 1.1659x; 1.1659x over previous
#include <cuda_runtime.h>
#include <cuda_fp16.h>
#include <cuda_bf16.h>
#include <cstddef>
#include <cstdint>

// ---------------- problem constants ----------------
#define NN 20000
#define EE 240000
#define GG 128
#define F_IN 128
#define EMB 256
#define HH 2
#define HC 512          // H*EMB
#define DENSE 512
#define NCLS 10

// ---------------- scratch (device globals; no allocation) ----------------
#define OFF_H     0                         // [N,512]
#define OFF_GAT   (OFF_H   + NN*512)        // [N,512]
#define OFF_X     (OFF_GAT + NN*512)        // [N,256]
#define OFF_ALS   (OFF_X   + NN*256)        // [N,2]
#define OFF_ALD   (OFF_ALS + NN*2)          // [N,2]
#define OFF_POOL  (OFF_ALD + NN*2)          // [G,512] accumulated reps
#define OFF_DENSE (OFF_POOL + GG*512)       // [G,512]
#define FBUF_SZ   (OFF_DENSE + GG*512)

__device__ float g_fbuf[FBUF_SZ];

#define IOFF_DEG    0
#define IOFF_ROWS   (IOFF_DEG + NN)         // N+1
#define IOFF_WP     (IOFF_ROWS + NN + 1)    // N+1
#define IOFF_CSR    (IOFF_WP + NN + 1)      // E+N
#define IOFF_GSTART (IOFF_CSR + EE + NN)    // G+1
#define IBUF_SZ     (IOFF_GSTART + GG + 1)

__device__ int g_ibuf[IBUF_SZ];

// ---------------- init: deg=1 (self loop), zero pooled accumulator ----------------
__global__ void k_init(int* deg, float* pool) {
    int i = blockIdx.x * blockDim.x + threadIdx.x;
    if (i < NN) deg[i] = 1;
    if (i < GG * 512) pool[i] = 0.f;
}

// count in-degrees of real edges
__global__ void k_count(const int* __restrict__ ei, int* deg) {
    int e = blockIdx.x * blockDim.x + threadIdx.x;
    if (e < EE) atomicAdd(&deg[ei[EE + e]], 1);
}

// exclusive scan of deg[0..N) -> rows[0..N] AND wp[0..N], single block of 1024
#define SCAN_T 1024
__global__ void k_scan(const int* __restrict__ deg, int* rows, int* wp) {
    __shared__ int sh[SCAN_T];
    int tid = threadIdx.x;
    const int items = (NN + SCAN_T - 1) / SCAN_T;
    int start = tid * items;
    int local = 0;
    for (int i = 0; i < items; i++) {
        int idx = start + i;
        if (idx < NN) local += deg[idx];
    }
    sh[tid] = local;
    __syncthreads();
    for (int d = 1; d < SCAN_T; d <<= 1) {
        int v = (tid >= d) ? sh[tid - d] : 0;
        __syncthreads();
        sh[tid] += v;
        __syncthreads();
    }
    int run = sh[tid] - local;  // exclusive offset
    for (int i = 0; i < items; i++) {
        int idx = start + i;
        if (idx < NN) { rows[idx] = run; wp[idx] = run; run += deg[idx]; }
    }
    if (tid == SCAN_T - 1) { rows[NN] = sh[SCAN_T - 1]; wp[NN] = sh[SCAN_T - 1]; }
}

// scatter edges (and self loops) into CSR-by-dst
__global__ void k_scatter(const int* __restrict__ ei, int* wp, int* csr) {
    int i = blockIdx.x * blockDim.x + threadIdx.x;
    if (i >= EE + NN) return;
    int s, d;
    if (i < EE) { s = ei[i]; d = ei[EE + i]; }
    else        { s = d = i - EE; }
    int pos = atomicAdd(&wp[d], 1);
    csr[pos] = s;
}

// graph boundaries from sorted batch_index
__global__ void k_gstart(const int* __restrict__ batch, int* gstart) {
    int v = blockIdx.x * blockDim.x + threadIdx.x;
    if (v >= NN) return;
    int b = batch[v];
    if (v == 0) {
        for (int g = 0; g <= b; g++) gstart[g] = 0;
    } else {
        int bp = batch[v - 1];
        for (int g = bp + 1; g <= b; g++) gstart[g] = v;
    }
    if (v == NN - 1) {
        for (int g = b + 1; g <= GG; g++) gstart[g] = NN;
    }
}

// ---------------- fp16 tensor-core GEMM (m16n8k16), double-buffered --------
// C[M,Nc] = A[M,K] * B[K,Nc] (+bias)(+relu), fp32 accumulate.
// CTA tile 128x128, K-chunk 16; 8 warps (2M x 4N), warp tile 64x32 = 4x4 m16n8.
// Inputs converted fp32->fp16 (packed half2 along K) at smem-store time.
// A word [row][k2]: halves (2*k2, 2*k2+1) of that row. stride 12 -> frag LDS
// banks 12*gid+tig all distinct. B word [k2][col]: halves of rows (2k2,2k2+1)
// at col. stride 136 -> frag banks 8*tig+gid all distinct; staged via uint4.
// Static smem: 2 stages x (A 128x12 + B 8x136) words = 20992 B.

__device__ __forceinline__ uint32_t pack_h2(float x, float y) {
    __half2 h = __floats2half2_rn(x, y);
    return *reinterpret_cast<uint32_t*>(&h);
}

#define MMA_F16(c, a, b) \
    asm("mma.sync.aligned.m16n8k16.row.col.f32.f16.f16.f32 " \
        "{%0,%1,%2,%3}, {%4,%5,%6,%7}, {%8,%9}, {%0,%1,%2,%3};" \
        : "+f"((c)[0]), "+f"((c)[1]), "+f"((c)[2]), "+f"((c)[3]) \
        : "r"((a)[0]), "r"((a)[1]), "r"((a)[2]), "r"((a)[3]), \
          "r"((b)[0]), "r"((b)[1]))

#define AS_STRIDE 12                          // 8 half2 words + pad
#define BS_STRIDE 136                         // 128 words + pad (8 mod 32)
#define A_WORDS   (128 * AS_STRIDE)           // 1536
#define B_WORDS   (8 * BS_STRIDE)             // 1088
#define STAGE_SZ  (A_WORDS + B_WORDS)         // 2624 words = 10496 B

__global__ __launch_bounds__(256) void k_mma(
    const float* __restrict__ A, const float* __restrict__ B,
    const float* __restrict__ bias, float* __restrict__ C,
    int M, int K, int Nc, int doRelu)
{
    __shared__ uint32_t smem_st[2 * STAGE_SZ];   // 20992 B static

    int tid = threadIdx.x;
    int wid = tid >> 5, lane = tid & 31;
    int wm = (wid >> 2) * 64;       // 0 or 64
    int wn = (wid & 3) * 32;        // 0,32,64,96
    int gid = lane >> 2, tig = lane & 3;
    int rowBase = blockIdx.y * 128;
    int colBase = blockIdx.x * 128;

    // per-thread load coordinates (chunk = 16 K-cols)
    int a_r = tid >> 1, a_k = (tid & 1) * 8;       // row 0..127, K-offset 0/8
    int b_k2 = tid >> 5, b_c = (tid & 31) * 4;     // k2 0..7, col group

    float c[4][4][4];
#pragma unroll
    for (int mt = 0; mt < 4; mt++)
#pragma unroll
        for (int nt = 0; nt < 4; nt++)
#pragma unroll
            for (int r = 0; r < 4; r++) c[mt][nt][r] = 0.f;

    float4 ra0, ra1, rb0, rb1;
    // ---- load chunk 0 into regs ----
    {
        int gr = rowBase + a_r;
        if (gr < M) {
            ra0 = *(const float4*)(A + (size_t)gr * K + a_k);
            ra1 = *(const float4*)(A + (size_t)gr * K + a_k + 4);
        } else {
            ra0 = make_float4(0.f, 0.f, 0.f, 0.f); ra1 = ra0;
        }
        rb0 = *(const float4*)(B + (size_t)(2 * b_k2)     * Nc + colBase + b_c);
        rb1 = *(const float4*)(B + (size_t)(2 * b_k2 + 1) * Nc + colBase + b_c);
    }
    // ---- store chunk 0 into stage 0 ----
    {
        uint32_t* AsU = smem_st;
        uint32_t* BsU = smem_st + A_WORDS;
        uint32_t* da = &AsU[a_r * AS_STRIDE + (a_k >> 1)];
        da[0] = pack_h2(ra0.x, ra0.y); da[1] = pack_h2(ra0.z, ra0.w);
        da[2] = pack_h2(ra1.x, ra1.y); da[3] = pack_h2(ra1.z, ra1.w);
        uint4 bw = make_uint4(pack_h2(rb0.x, rb1.x), pack_h2(rb0.y, rb1.y),
                              pack_h2(rb0.z, rb1.z), pack_h2(rb0.w, rb1.w));
        *(uint4*)&BsU[b_k2 * BS_STRIDE + b_c] = bw;
    }
    __syncthreads();

    int nchunks = K >> 4;
    for (int ch = 0; ch < nchunks; ch++) {
        int cur = ch & 1;
        uint32_t* AsU = smem_st + cur * STAGE_SZ;
        uint32_t* BsU = AsU + A_WORDS;
        bool havenext = (ch + 1 < nchunks);
        // prefetch next chunk (LDGs overlap the MMAs below)
        if (havenext) {
            int k0 = (ch + 1) << 4;
            int gr = rowBase + a_r;
            if (gr < M) {
                ra0 = *(const float4*)(A + (size_t)gr * K + k0 + a_k);
                ra1 = *(const float4*)(A + (size_t)gr * K + k0 + a_k + 4);
            } else {
                ra0 = make_float4(0.f, 0.f, 0.f, 0.f); ra1 = ra0;
            }
            rb0 = *(const float4*)(B + (size_t)(k0 + 2 * b_k2)     * Nc + colBase + b_c);
            rb1 = *(const float4*)(B + (size_t)(k0 + 2 * b_k2 + 1) * Nc + colBase + b_c);
        }
        // ---- compute: one m16n8k16 step over the 16-wide chunk ----
        {
            uint32_t a[4][4], b[4][2];
#pragma unroll
            for (int mt = 0; mt < 4; mt++) {
                int r0 = wm + mt * 16 + gid;
                a[mt][0] = AsU[(r0)     * AS_STRIDE + tig];
                a[mt][1] = AsU[(r0 + 8) * AS_STRIDE + tig];
                a[mt][2] = AsU[(r0)     * AS_STRIDE + tig + 4];
                a[mt][3] = AsU[(r0 + 8) * AS_STRIDE + tig + 4];
            }
#pragma unroll
            for (int nt = 0; nt < 4; nt++) {
                int cc = wn + nt * 8 + gid;
                b[nt][0] = BsU[(tig)     * BS_STRIDE + cc];
                b[nt][1] = BsU[(tig + 4) * BS_STRIDE + cc];
            }
#pragma unroll
            for (int mt = 0; mt < 4; mt++)
#pragma unroll
                for (int nt = 0; nt < 4; nt++)
                    MMA_F16(c[mt][nt], a[mt], b[nt]);
        }
        // ---- stage next chunk into alternate buffer ----
        if (havenext) {
            uint32_t* AsN = smem_st + (cur ^ 1) * STAGE_SZ;
            uint32_t* BsN = AsN + A_WORDS;
            uint32_t* da = &AsN[a_r * AS_STRIDE + (a_k >> 1)];
            da[0] = pack_h2(ra0.x, ra0.y); da[1] = pack_h2(ra0.z, ra0.w);
            da[2] = pack_h2(ra1.x, ra1.y); da[3] = pack_h2(ra1.z, ra1.w);
            uint4 bw = make_uint4(pack_h2(rb0.x, rb1.x), pack_h2(rb0.y, rb1.y),
                                  pack_h2(rb0.z, rb1.z), pack_h2(rb0.w, rb1.w));
            *(uint4*)&BsN[b_k2 * BS_STRIDE + b_c] = bw;
        }
        __syncthreads();
    }

    // ---- epilogue ----
#pragma unroll
    for (int mt = 0; mt < 4; mt++) {
        int r0 = rowBase + wm + mt * 16 + gid;
        int r1 = r0 + 8;
#pragma unroll
        for (int nt = 0; nt < 4; nt++) {
            int cc = colBase + wn + nt * 8 + 2 * tig;
            float2 v0 = make_float2(c[mt][nt][0], c[mt][nt][1]);
            float2 v1 = make_float2(c[mt][nt][2], c[mt][nt][3]);
            if (bias) {
                float b0 = bias[cc], b1 = bias[cc + 1];
                v0.x += b0; v0.y += b1; v1.x += b0; v1.y += b1;
            }
            if (doRelu) {
                v0.x = fmaxf(v0.x, 0.f); v0.y = fmaxf(v0.y, 0.f);
                v1.x = fmaxf(v1.x, 0.f); v1.y = fmaxf(v1.y, 0.f);
            }
            if (r0 < M) *(float2*)(C + (size_t)r0 * Nc + cc) = v0;
            if (r1 < M) *(float2*)(C + (size_t)r1 * Nc + cc) = v1;
        }
    }
}

// ---------------- per-node attention logit terms ----------------
__global__ void k_al(const float* __restrict__ h, const float* __restrict__ asrc,
                     const float* __restrict__ adst, float* __restrict__ als,
                     float* __restrict__ ald)
{
    int warp = (blockIdx.x * blockDim.x + threadIdx.x) >> 5;
    int lane = threadIdx.x & 31;
    if (warp >= NN) return;
    const float* hr = h + (size_t)warp * 512;
    float s0 = 0.f, s1 = 0.f, d0 = 0.f, d1 = 0.f;
#pragma unroll
    for (int i = 0; i < 8; i++) {
        int c = i * 32 + lane;
        float h0 = hr[c], h1 = hr[256 + c];
        s0 += h0 * asrc[c];        d0 += h0 * adst[c];
        s1 += h1 * asrc[256 + c];  d1 += h1 * adst[256 + c];
    }
#pragma unroll
    for (int off = 16; off; off >>= 1) {
        s0 += __shfl_xor_sync(0xffffffffu, s0, off);
        s1 += __shfl_xor_sync(0xffffffffu, s1, off);
        d0 += __shfl_xor_sync(0xffffffffu, d0, off);
        d1 += __shfl_xor_sync(0xffffffffu, d1, off);
    }
    if (lane == 0) {
        als[warp * 2] = s0; als[warp * 2 + 1] = s1;
        ald[warp * 2] = d0; ald[warp * 2 + 1] = d1;
    }
}

// ---------------- attention softmax + aggregation (one warp per dst node) -----------
__global__ void k_attn(const float* __restrict__ h, const float* __restrict__ als,
                       const float* __restrict__ ald, const float* __restrict__ bvec,
                       const int* __restrict__ rows, const int* __restrict__ csr,
                       float* __restrict__ out)
{
    int warp = (blockIdx.x * blockDim.x + threadIdx.x) >> 5;
    int lane = threadIdx.x & 31;
    if (warp >= NN) return;
    int v = warp;
    int s0 = rows[v], s1 = rows[v + 1];
    int deg = s1 - s0;
    float ad0 = ald[v * 2], ad1 = ald[v * 2 + 1];

    // pass 1: max logit per head
    float m0 = -1e30f, m1 = -1e30f;
    for (int base = 0; base < deg; base += 32) {
        int j = base + lane;
        if (j < deg) {
            int s = csr[s0 + j];
            float t0 = als[s * 2] + ad0;     t0 = fmaxf(t0, 0.2f * t0);
            float t1 = als[s * 2 + 1] + ad1; t1 = fmaxf(t1, 0.2f * t1);
            m0 = fmaxf(m0, t0); m1 = fmaxf(m1, t1);
        }
    }
#pragma unroll
    for (int off = 16; off; off >>= 1) {
        m0 = fmaxf(m0, __shfl_xor_sync(0xffffffffu, m0, off));
        m1 = fmaxf(m1, __shfl_xor_sync(0xffffffffu, m1, off));
    }

    // pass 2: exp weights + weighted aggregation, 2 edges/iter for load MLP
    float acc[16];
#pragma unroll
    for (int k = 0; k < 16; k++) acc[k] = 0.f;
    float den0 = 0.f, den1 = 0.f;
    int j = 0;
    for (; j + 2 <= deg; j += 2) {
        int sa = csr[s0 + j];
        int sb = csr[s0 + j + 1];
        float ta0 = als[sa * 2] + ad0;     ta0 = fmaxf(ta0, 0.2f * ta0);
        float ta1 = als[sa * 2 + 1] + ad1; ta1 = fmaxf(ta1, 0.2f * ta1);
        float tb0 = als[sb * 2] + ad0;     tb0 = fmaxf(tb0, 0.2f * tb0);
        float tb1 = als[sb * 2 + 1] + ad1; tb1 = fmaxf(tb1, 0.2f * tb1);
        float wa0 = __expf(ta0 - m0), wa1 = __expf(ta1 - m1);
        float wb0 = __expf(tb0 - m0), wb1 = __expf(tb1 - m1);
        den0 += wa0 + wb0; den1 += wa1 + wb1;
        const float* ha = h + (size_t)sa * 512 + lane;
        const float* hb = h + (size_t)sb * 512 + lane;
#pragma unroll
        for (int k = 0; k < 16; k++) {
            float va = ha[k * 32];
            float vb = hb[k * 32];
            acc[k] += (k < 8 ? wa0 : wa1) * va + (k < 8 ? wb0 : wb1) * vb;
        }
    }
    for (; j < deg; j++) {
        int s = csr[s0 + j];
        float t0 = als[s * 2] + ad0;     t0 = fmaxf(t0, 0.2f * t0);
        float t1 = als[s * 2 + 1] + ad1; t1 = fmaxf(t1, 0.2f * t1);
        float w0 = __expf(t0 - m0), w1 = __expf(t1 - m1);
        den0 += w0; den1 += w1;
        const float* hr = h + (size_t)s * 512 + lane;
#pragma unroll
        for (int k = 0; k < 16; k++)
            acc[k] += (k < 8 ? w0 : w1) * hr[k * 32];
    }
    float r0 = 1.0f / den0, r1 = 1.0f / den1;
    float* orow = out + (size_t)v * 512 + lane;
#pragma unroll
    for (int k = 0; k < 16; k++) {
        float val = acc[k] * (k < 8 ? r0 : r1) + bvec[k * 32 + lane];
        orow[k * 32] = fmaxf(val, 0.f);   // fused relu (post-GAT)
    }
}

// ---------------- pooling: per-graph max + mean, accumulated across layers ----------
__global__ void k_pool(const float* __restrict__ x, const int* __restrict__ gstart,
                       float* __restrict__ gacc)
{
    int g = blockIdx.x;
    int c = threadIdx.x;   // 256
    int s = gstart[g], e = gstart[g + 1];
    float mx = 0.f, sm = 0.f;   // post-relu values are >= 0
    int v = s;
    for (; v + 2 <= e; v += 2) {
        float a = x[(size_t)v * 256 + c];
        float b = x[(size_t)(v + 1) * 256 + c];
        sm += a + b; mx = fmaxf(mx, fmaxf(a, b));
    }
    if (v < e) {
        float a = x[(size_t)v * 256 + c];
        sm += a; mx = fmaxf(mx, a);
    }
    int cnt = e - s;
    float mean = (cnt > 0) ? sm / (float)cnt : 0.f;
    gacc[g * 512 + c]       += mx;
    gacc[g * 512 + 256 + c] += mean;
}

// ---------------- final tiny linear: [G,512] @ [512,10] + b ----------------
__global__ void k_line2(const float* __restrict__ gd, const float* __restrict__ W,
                        const float* __restrict__ b, float* __restrict__ out)
{
    __shared__ float sh[512];
    int g = blockIdx.x;
    for (int i = threadIdx.x; i < 512; i += blockDim.x) sh[i] = gd[g * 512 + i];
    __syncthreads();
    if (threadIdx.x < NCLS) {
        float acc = b[threadIdx.x];
        for (int k = 0; k < 512; k++) acc += sh[k] * W[k * NCLS + threadIdx.x];
        out[g * NCLS + threadIdx.x] = acc;
    }
}

// ---------------- host orchestration ----------------
extern "C" void kernel_launch(void* const* d_in, const int* in_sizes, int n_in,
                              void* d_out, int out_size)
{
    const float* x_in  = (const float*)d_in[0];
    const int*   ei    = (const int*)d_in[1];
    const int*   batch = (const int*)d_in[2];
    const float* attW[3]  = {(const float*)d_in[3],  (const float*)d_in[9],  (const float*)d_in[15]};
    const float* asrc[3]  = {(const float*)d_in[4],  (const float*)d_in[10], (const float*)d_in[16]};
    const float* adst[3]  = {(const float*)d_in[5],  (const float*)d_in[11], (const float*)d_in[17]};
    const float* attb[3]  = {(const float*)d_in[6],  (const float*)d_in[12], (const float*)d_in[18]};
    const float* linW[3]  = {(const float*)d_in[7],  (const float*)d_in[13], (const float*)d_in[19]};
    const float* linb[3]  = {(const float*)d_in[8],  (const float*)d_in[14], (const float*)d_in[20]};
    const float* line1W = (const float*)d_in[21];
    const float* line1b = (const float*)d_in[22];
    const float* line2W = (const float*)d_in[23];
    const float* line2b = (const float*)d_in[24];
    float* out = (float*)d_out;

    static float* fbuf = nullptr;
    static int*   ibuf = nullptr;
    if (!fbuf) {
        cudaGetSymbolAddress((void**)&fbuf, g_fbuf);
        cudaGetSymbolAddress((void**)&ibuf, g_ibuf);
    }

    float* bh    = fbuf + OFF_H;
    float* bgat  = fbuf + OFF_GAT;
    float* bx    = fbuf + OFF_X;
    float* bals  = fbuf + OFF_ALS;
    float* bald  = fbuf + OFF_ALD;
    float* bpool = fbuf + OFF_POOL;
    float* bdense= fbuf + OFF_DENSE;
    int* deg    = ibuf + IOFF_DEG;
    int* rows   = ibuf + IOFF_ROWS;
    int* wp     = ibuf + IOFF_WP;
    int* csr    = ibuf + IOFF_CSR;
    int* gstart = ibuf + IOFF_GSTART;

    int mtiles = (NN + 127) / 128;

    // ---- preprocessing part 1 (launch idx 0..2) ----
    {
        int n = GG * 512;  // >= NN
        k_init<<<(n + 255) / 256, 256>>>(deg, bpool);
        k_count<<<(EE + 255) / 256, 256>>>(ei, deg);
        k_scan<<<1, SCAN_T>>>(deg, rows, wp);
    }

    // ---- layer-1 h GEMM at launch idx 3 (profiled slot; independent of CSR) ----
    {
        dim3 grid(HC / 128, mtiles);
        k_mma<<<grid, 256>>>(x_in, attW[0], nullptr, bh, NN, F_IN, HC, 0);
    }

    // ---- preprocessing part 2 ----
    k_scatter<<<(EE + NN + 255) / 256, 256>>>(ei, wp, csr);
    k_gstart<<<(NN + 255) / 256, 256>>>(batch, gstart);

    // ---- three GAT layers ----
    const float* xcur = x_in;
    int fin = F_IN;
    for (int i = 0; i < 3; i++) {
        // h = x @ W (layer 0 already launched above)
        if (i > 0) {
            dim3 grid(HC / 128, mtiles);
            k_mma<<<grid, 256>>>(xcur, attW[i], nullptr, bh, NN, fin, HC, 0);
        }
        // per-node attention terms
        k_al<<<(NN * 32 + 255) / 256, 256>>>(bh, asrc[i], adst[i], bals, bald);
        // softmax-attention aggregation (+ bias + relu)
        k_attn<<<(NN * 32 + 255) / 256, 256>>>(bh, bals, bald, attb[i], rows, csr, bgat);
        // x = relu(gat @ lin_W + lin_b)   [N,512] x [512,256]
        {
            dim3 grid(EMB / 128, mtiles);
            k_mma<<<grid, 256>>>(bgat, linW[i], linb[i], bx, NN, HC, EMB, 1);
        }
        // pooling accumulation
        k_pool<<<GG, 256>>>(bx, gstart, bpool);
        xcur = bx;
        fin = EMB;
    }

    // ---- MLP head ----
    {
        dim3 grid(DENSE / 128, 1);
        k_mma<<<grid, 256>>>(bpool, line1W, line1b, bdense, GG, 2 * EMB, DENSE, 1);
    }
    k_line2<<<GG, 512>>>(bdense, line2W, line2b, out);
}

// round 17
// speedup vs baseline: 1.3302x; 1.1410x over previous
#include <cuda_runtime.h>
#include <cuda_fp16.h>
#include <cuda_bf16.h>
#include <cstddef>
#include <cstdint>

// ---------------- problem constants ----------------
#define NN 20000
#define EE 240000
#define GG 128
#define F_IN 128
#define EMB 256
#define HH 2
#define HC 512          // H*EMB
#define DENSE 512
#define NCLS 10

// ---------------- fp32 scratch ----------------
#define OFF_H     0                         // [N,512]
#define OFF_X     (OFF_H   + NN*512)        // [N,256]
#define OFF_ALS   (OFF_X   + NN*256)        // [N,2]
#define OFF_ALD   (OFF_ALS + NN*2)          // [N,2]
#define OFF_POOL  (OFF_ALD + NN*2)          // [G,512]
#define OFF_DENSE (OFF_POOL + GG*512)       // [G,512]
#define FBUF_SZ   (OFF_DENSE + GG*512)

__device__ float g_fbuf[FBUF_SZ];

// ---------------- fp16 scratch (layout matches k_cvt8 linear index) -------
#define HOFF_XH     0                        // [N,128]
#define HOFF_ATTW0  2560000                  // 128*512
#define HOFF_ATTW1  2625536                  // 256*512
#define HOFF_ATTW2  2756608                  // 256*512
#define HOFF_LINW0  2887680                  // 512*256
#define HOFF_LINW1  3018752
#define HOFF_LINW2  3149824
#define HOFF_L1W    3280896                  // 512*512
#define CVT_TOTAL   3543040
#define HOFF_BGAT   3543040                  // [N,512]
#define HOFF_BXH    13783040                 // [N,256]
#define HOFF_BPOOL  18903040                 // [G,512]
#define HBUF_SZ     18968576

__device__ __half g_hbuf[HBUF_SZ];

#define IOFF_DEG    0
#define IOFF_ROWS   (IOFF_DEG + NN)         // N+1
#define IOFF_WP     (IOFF_ROWS + NN + 1)    // N+1
#define IOFF_CSR    (IOFF_WP + NN + 1)      // E+N
#define IOFF_GSTART (IOFF_CSR + EE + NN)    // G+1
#define IBUF_SZ     (IOFF_GSTART + GG + 1)

__device__ int g_ibuf[IBUF_SZ];

// ---------------- init ----------------
__global__ void k_init(int* deg, float* pool) {
    int i = blockIdx.x * blockDim.x + threadIdx.x;
    if (i < NN) deg[i] = 1;
    if (i < GG * 512) pool[i] = 0.f;
}

__global__ void k_count(const int* __restrict__ ei, int* deg) {
    int e = blockIdx.x * blockDim.x + threadIdx.x;
    if (e < EE) atomicAdd(&deg[ei[EE + e]], 1);
}

#define SCAN_T 1024
__global__ void k_scan(const int* __restrict__ deg, int* rows, int* wp) {
    __shared__ int sh[SCAN_T];
    int tid = threadIdx.x;
    const int items = (NN + SCAN_T - 1) / SCAN_T;
    int start = tid * items;
    int local = 0;
    for (int i = 0; i < items; i++) {
        int idx = start + i;
        if (idx < NN) local += deg[idx];
    }
    sh[tid] = local;
    __syncthreads();
    for (int d = 1; d < SCAN_T; d <<= 1) {
        int v = (tid >= d) ? sh[tid - d] : 0;
        __syncthreads();
        sh[tid] += v;
        __syncthreads();
    }
    int run = sh[tid] - local;
    for (int i = 0; i < items; i++) {
        int idx = start + i;
        if (idx < NN) { rows[idx] = run; wp[idx] = run; run += deg[idx]; }
    }
    if (tid == SCAN_T - 1) { rows[NN] = sh[SCAN_T - 1]; wp[NN] = sh[SCAN_T - 1]; }
}

__global__ void k_scatter(const int* __restrict__ ei, int* wp, int* csr) {
    int i = blockIdx.x * blockDim.x + threadIdx.x;
    if (i >= EE + NN) return;
    int s, d;
    if (i < EE) { s = ei[i]; d = ei[EE + i]; }
    else        { s = d = i - EE; }
    int pos = atomicAdd(&wp[d], 1);
    csr[pos] = s;
}

__global__ void k_gstart(const int* __restrict__ batch, int* gstart) {
    int v = blockIdx.x * blockDim.x + threadIdx.x;
    if (v >= NN) return;
    int b = batch[v];
    if (v == 0) {
        for (int g = 0; g <= b; g++) gstart[g] = 0;
    } else {
        int bp = batch[v - 1];
        for (int g = bp + 1; g <= b; g++) gstart[g] = v;
    }
    if (v == NN - 1) {
        for (int g = b + 1; g <= GG; g++) gstart[g] = NN;
    }
}

// ---------------- fp32 -> fp16 conversion (x + 7 weight matrices) ----------
__global__ void k_cvt8(const float* __restrict__ x,
                       const float* __restrict__ w0, const float* __restrict__ w1,
                       const float* __restrict__ w2, const float* __restrict__ l0,
                       const float* __restrict__ l1, const float* __restrict__ l2,
                       const float* __restrict__ m1)
{
    int idx4 = blockIdx.x * blockDim.x + threadIdx.x;
    if (idx4 >= CVT_TOTAL / 4) return;
    int i = idx4 * 4;
    const float* src; int off;
    if      (i < HOFF_ATTW0) { src = x;  off = i; }
    else if (i < HOFF_ATTW1) { src = w0; off = i - HOFF_ATTW0; }
    else if (i < HOFF_ATTW2) { src = w1; off = i - HOFF_ATTW1; }
    else if (i < HOFF_LINW0) { src = w2; off = i - HOFF_ATTW2; }
    else if (i < HOFF_LINW1) { src = l0; off = i - HOFF_LINW0; }
    else if (i < HOFF_LINW2) { src = l1; off = i - HOFF_LINW1; }
    else if (i < HOFF_L1W)   { src = l2; off = i - HOFF_LINW2; }
    else                     { src = m1; off = i - HOFF_L1W; }
    float4 v = *(const float4*)(src + off);
    __half2* dst = (__half2*)(g_hbuf + i);
    dst[0] = __floats2half2_rn(v.x, v.y);
    dst[1] = __floats2half2_rn(v.z, v.w);
}

__global__ void k_cvt(const float* __restrict__ src, __half* __restrict__ dst, int n) {
    int i = blockIdx.x * blockDim.x + threadIdx.x;
    if (i < n) dst[i] = __float2half(src[i]);
}

// ---------------- fp16 GEMM: cp.async 4-stage + ldmatrix -------------------
// C[M,Nc] = A[M,K]*B[K,Nc] (+bias)(+relu), fp32 acc; optional fp16 copy Ch.
// CTA 128x128, chunk K=16; 8 warps (2Mx4N), warp 64x32 = 4x4 m16n8k16.
// A smem: 128 rows x 12 words (8 data half2 + pad); B smem: 16 rows x 68
// words (64 data + pad). Both cp.async-16B aligned and ldmatrix-phase
// conflict-free (48B*r mod 128 and 272B*r mod 128 cover all banks).

#define MMA_F16(c, a, b) \
    asm("mma.sync.aligned.m16n8k16.row.col.f32.f16.f16.f32 " \
        "{%0,%1,%2,%3}, {%4,%5,%6,%7}, {%8,%9}, {%0,%1,%2,%3};" \
        : "+f"((c)[0]), "+f"((c)[1]), "+f"((c)[2]), "+f"((c)[3]) \
        : "r"((a)[0]), "r"((a)[1]), "r"((a)[2]), "r"((a)[3]), \
          "r"((b)[0]), "r"((b)[1]))

#define LDSM_X4(r0, r1, r2, r3, addr) \
    asm volatile("ldmatrix.sync.aligned.m8n8.x4.shared.b16 {%0,%1,%2,%3}, [%4];" \
        : "=r"(r0), "=r"(r1), "=r"(r2), "=r"(r3) : "r"(addr))

#define LDSM_X2_T(r0, r1, addr) \
    asm volatile("ldmatrix.sync.aligned.m8n8.x2.trans.shared.b16 {%0,%1}, [%2];" \
        : "=r"(r0), "=r"(r1) : "r"(addr))

#define CP_ASYNC16(dst, src, sz) \
    asm volatile("cp.async.cg.shared.global [%0], [%1], 16, %2;" \
        :: "r"(dst), "l"(src), "r"(sz))
#define CP_COMMIT() asm volatile("cp.async.commit_group;")
#define CP_WAIT(n)  asm volatile("cp.async.wait_group %0;" :: "n"(n))

#define AQ_ST 12                              // words per A row
#define BQ_ST 68                              // words per B row
#define AQ_WORDS (128 * AQ_ST)                // 1536
#define QSTAGE   (AQ_WORDS + 16 * BQ_ST)      // 1536+1088 = 2624 words
#define NSTAGE   4                            // 4*10496B = 41984B

__global__ __launch_bounds__(256) void k_mma(
    const __half* __restrict__ A, const __half* __restrict__ B,
    const float* __restrict__ bias, float* __restrict__ C,
    __half* __restrict__ Ch, int M, int K, int Nc, int doRelu)
{
    __shared__ uint32_t smem_st[NSTAGE * QSTAGE];

    int tid = threadIdx.x;
    int wid = tid >> 5, lane = tid & 31;
    int wm = (wid >> 2) * 64;
    int wn = (wid & 3) * 32;
    int gid = lane >> 2, tig = lane & 3;
    int rowBase = blockIdx.y * 128;
    int colBase = blockIdx.x * 128;

    uint32_t smem_u32 = (uint32_t)__cvta_generic_to_shared(smem_st);

    // cp.async per-thread coordinates
    int ca_row = tid >> 1, ca_seg = tid & 1;         // A: row, 16B half
    int cb_row = tid >> 4, cb_seg = tid & 15;        // B: k-row, 16B segment
    int a_grow = rowBase + ca_row;
    const __half* a_src_base = A + (size_t)a_grow * K + ca_seg * 8;
    uint32_t a_dst_off = (uint32_t)(ca_row * AQ_ST + ca_seg * 4) * 4;
    int a_sz = (a_grow < M) ? 16 : 0;
    const __half* b_src_base = B + (size_t)cb_row * Nc + colBase + cb_seg * 8;
    uint32_t b_dst_off = (uint32_t)(AQ_WORDS + cb_row * BQ_ST + cb_seg * 4) * 4;

    int nchunks = K >> 4;

    // ---- prologue: stage first min(3, nchunks) chunks ----
    int issued = 0;
    int pro = nchunks < 3 ? nchunks : 3;
    for (; issued < pro; issued++) {
        uint32_t sb = smem_u32 + (uint32_t)((issued & 3) * QSTAGE) * 4;
        CP_ASYNC16(sb + a_dst_off, a_src_base + issued * 16, a_sz);
        CP_ASYNC16(sb + b_dst_off, b_src_base + (size_t)(issued * 16) * Nc, 16);
        CP_COMMIT();
    }

    float c[4][4][4];
#pragma unroll
    for (int mt = 0; mt < 4; mt++)
#pragma unroll
        for (int nt = 0; nt < 4; nt++)
#pragma unroll
            for (int r = 0; r < 4; r++) c[mt][nt][r] = 0.f;

    // ldmatrix lane addressing (within a stage)
    int a_lrow = lane & 15;                    // row within 16-row mt tile
    uint32_t a_koff = (uint32_t)(lane >> 4) * 16;  // bytes (4 words * 4B / ... 8 halves=16B)
    int b_lrow = lane & 15;                    // k row 0..15

    for (int ch = 0; ch < nchunks; ch++) {
        // wait for chunk ch (allow up to min(2, remaining) newer groups pending)
        int ahead = nchunks - 1 - ch;
        if (ahead >= 2)      { CP_WAIT(2); }
        else if (ahead == 1) { CP_WAIT(1); }
        else                 { CP_WAIT(0); }
        __syncthreads();

        // issue chunk `issued` into its slot (prev occupant fully consumed)
        if (issued < nchunks) {
            uint32_t sb = smem_u32 + (uint32_t)((issued & 3) * QSTAGE) * 4;
            CP_ASYNC16(sb + a_dst_off, a_src_base + issued * 16, a_sz);
            CP_ASYNC16(sb + b_dst_off, b_src_base + (size_t)(issued * 16) * Nc, 16);
            CP_COMMIT();
            issued++;
        }

        // ---- compute chunk ch ----
        uint32_t sbase = smem_u32 + (uint32_t)((ch & 3) * QSTAGE) * 4;
        uint32_t a[4][4], b[4][2];
#pragma unroll
        for (int mt = 0; mt < 4; mt++) {
            uint32_t aw = sbase + (uint32_t)((wm + mt * 16 + a_lrow) * AQ_ST) * 4 + a_koff;
            LDSM_X4(a[mt][0], a[mt][1], a[mt][2], a[mt][3], aw);
        }
#pragma unroll
        for (int nt = 0; nt < 4; nt++) {
            uint32_t bw = sbase + (uint32_t)(AQ_WORDS + b_lrow * BQ_ST) * 4
                        + (uint32_t)(wn + nt * 8) * 2;
            LDSM_X2_T(b[nt][0], b[nt][1], bw);
        }
#pragma unroll
        for (int mt = 0; mt < 4; mt++)
#pragma unroll
            for (int nt = 0; nt < 4; nt++)
                MMA_F16(c[mt][nt], a[mt], b[nt]);
    }

    // ---- epilogue ----
#pragma unroll
    for (int mt = 0; mt < 4; mt++) {
        int r0 = rowBase + wm + mt * 16 + gid;
        int r1 = r0 + 8;
#pragma unroll
        for (int nt = 0; nt < 4; nt++) {
            int cc = colBase + wn + nt * 8 + 2 * tig;
            float2 v0 = make_float2(c[mt][nt][0], c[mt][nt][1]);
            float2 v1 = make_float2(c[mt][nt][2], c[mt][nt][3]);
            if (bias) {
                float b0 = bias[cc], b1 = bias[cc + 1];
                v0.x += b0; v0.y += b1; v1.x += b0; v1.y += b1;
            }
            if (doRelu) {
                v0.x = fmaxf(v0.x, 0.f); v0.y = fmaxf(v0.y, 0.f);
                v1.x = fmaxf(v1.x, 0.f); v1.y = fmaxf(v1.y, 0.f);
            }
            if (r0 < M) {
                *(float2*)(C + (size_t)r0 * Nc + cc) = v0;
                if (Ch) *(__half2*)(Ch + (size_t)r0 * Nc + cc) = __floats2half2_rn(v0.x, v0.y);
            }
            if (r1 < M) {
                *(float2*)(C + (size_t)r1 * Nc + cc) = v1;
                if (Ch) *(__half2*)(Ch + (size_t)r1 * Nc + cc) = __floats2half2_rn(v1.x, v1.y);
            }
        }
    }
}

// ---------------- per-node attention logit terms ----------------
__global__ void k_al(const float* __restrict__ h, const float* __restrict__ asrc,
                     const float* __restrict__ adst, float* __restrict__ als,
                     float* __restrict__ ald)
{
    int warp = (blockIdx.x * blockDim.x + threadIdx.x) >> 5;
    int lane = threadIdx.x & 31;
    if (warp >= NN) return;
    const float* hr = h + (size_t)warp * 512;
    float s0 = 0.f, s1 = 0.f, d0 = 0.f, d1 = 0.f;
#pragma unroll
    for (int i = 0; i < 8; i++) {
        int c = i * 32 + lane;
        float h0 = hr[c], h1 = hr[256 + c];
        s0 += h0 * asrc[c];        d0 += h0 * adst[c];
        s1 += h1 * asrc[256 + c];  d1 += h1 * adst[256 + c];
    }
#pragma unroll
    for (int off = 16; off; off >>= 1) {
        s0 += __shfl_xor_sync(0xffffffffu, s0, off);
        s1 += __shfl_xor_sync(0xffffffffu, s1, off);
        d0 += __shfl_xor_sync(0xffffffffu, d0, off);
        d1 += __shfl_xor_sync(0xffffffffu, d1, off);
    }
    if (lane == 0) {
        als[warp * 2] = s0; als[warp * 2 + 1] = s1;
        ald[warp * 2] = d0; ald[warp * 2 + 1] = d1;
    }
}

// ---------------- attention softmax + aggregation (fp16 output) -----------
__global__ void k_attn(const float* __restrict__ h, const float* __restrict__ als,
                       const float* __restrict__ ald, const float* __restrict__ bvec,
                       const int* __restrict__ rows, const int* __restrict__ csr,
                       __half* __restrict__ out)
{
    int warp = (blockIdx.x * blockDim.x + threadIdx.x) >> 5;
    int lane = threadIdx.x & 31;
    if (warp >= NN) return;
    int v = warp;
    int s0 = rows[v], s1 = rows[v + 1];
    int deg = s1 - s0;
    float ad0 = ald[v * 2], ad1 = ald[v * 2 + 1];

    float m0 = -1e30f, m1 = -1e30f;
    for (int base = 0; base < deg; base += 32) {
        int j = base + lane;
        if (j < deg) {
            int s = csr[s0 + j];
            float t0 = als[s * 2] + ad0;     t0 = fmaxf(t0, 0.2f * t0);
            float t1 = als[s * 2 + 1] + ad1; t1 = fmaxf(t1, 0.2f * t1);
            m0 = fmaxf(m0, t0); m1 = fmaxf(m1, t1);
        }
    }
#pragma unroll
    for (int off = 16; off; off >>= 1) {
        m0 = fmaxf(m0, __shfl_xor_sync(0xffffffffu, m0, off));
        m1 = fmaxf(m1, __shfl_xor_sync(0xffffffffu, m1, off));
    }

    float acc[16];
#pragma unroll
    for (int k = 0; k < 16; k++) acc[k] = 0.f;
    float den0 = 0.f, den1 = 0.f;
    int j = 0;
    for (; j + 2 <= deg; j += 2) {
        int sa = csr[s0 + j];
        int sb = csr[s0 + j + 1];
        float ta0 = als[sa * 2] + ad0;     ta0 = fmaxf(ta0, 0.2f * ta0);
        float ta1 = als[sa * 2 + 1] + ad1; ta1 = fmaxf(ta1, 0.2f * ta1);
        float tb0 = als[sb * 2] + ad0;     tb0 = fmaxf(tb0, 0.2f * tb0);
        float tb1 = als[sb * 2 + 1] + ad1; tb1 = fmaxf(tb1, 0.2f * tb1);
        float wa0 = __expf(ta0 - m0), wa1 = __expf(ta1 - m1);
        float wb0 = __expf(tb0 - m0), wb1 = __expf(tb1 - m1);
        den0 += wa0 + wb0; den1 += wa1 + wb1;
        const float* ha = h + (size_t)sa * 512 + lane;
        const float* hb = h + (size_t)sb * 512 + lane;
#pragma unroll
        for (int k = 0; k < 16; k++) {
            float va = ha[k * 32];
            float vb = hb[k * 32];
            acc[k] += (k < 8 ? wa0 : wa1) * va + (k < 8 ? wb0 : wb1) * vb;
        }
    }
    for (; j < deg; j++) {
        int s = csr[s0 + j];
        float t0 = als[s * 2] + ad0;     t0 = fmaxf(t0, 0.2f * t0);
        float t1 = als[s * 2 + 1] + ad1; t1 = fmaxf(t1, 0.2f * t1);
        float w0 = __expf(t0 - m0), w1 = __expf(t1 - m1);
        den0 += w0; den1 += w1;
        const float* hr = h + (size_t)s * 512 + lane;
#pragma unroll
        for (int k = 0; k < 16; k++)
            acc[k] += (k < 8 ? w0 : w1) * hr[k * 32];
    }
    float r0 = 1.0f / den0, r1 = 1.0f / den1;
    __half* orow = out + (size_t)v * 512 + lane;
#pragma unroll
    for (int k = 0; k < 16; k++) {
        float val = acc[k] * (k < 8 ? r0 : r1) + bvec[k * 32 + lane];
        orow[k * 32] = __float2half(fmaxf(val, 0.f));
    }
}

// ---------------- pooling ----------------
__global__ void k_pool(const float* __restrict__ x, const int* __restrict__ gstart,
                       float* __restrict__ gacc)
{
    int g = blockIdx.x;
    int c = threadIdx.x;   // 256
    int s = gstart[g], e = gstart[g + 1];
    float mx = 0.f, sm = 0.f;
    int v = s;
    for (; v + 2 <= e; v += 2) {
        float a = x[(size_t)v * 256 + c];
        float b = x[(size_t)(v + 1) * 256 + c];
        sm += a + b; mx = fmaxf(mx, fmaxf(a, b));
    }
    if (v < e) {
        float a = x[(size_t)v * 256 + c];
        sm += a; mx = fmaxf(mx, a);
    }
    int cnt = e - s;
    float mean = (cnt > 0) ? sm / (float)cnt : 0.f;
    gacc[g * 512 + c]       += mx;
    gacc[g * 512 + 256 + c] += mean;
}

// ---------------- final tiny linear ----------------
__global__ void k_line2(const float* __restrict__ gd, const float* __restrict__ W,
                        const float* __restrict__ b, float* __restrict__ out)
{
    __shared__ float sh[512];
    int g = blockIdx.x;
    for (int i = threadIdx.x; i < 512; i += blockDim.x) sh[i] = gd[g * 512 + i];
    __syncthreads();
    if (threadIdx.x < NCLS) {
        float acc = b[threadIdx.x];
        for (int k = 0; k < 512; k++) acc += sh[k] * W[k * NCLS + threadIdx.x];
        out[g * NCLS + threadIdx.x] = acc;
    }
}

// ---------------- host orchestration ----------------
extern "C" void kernel_launch(void* const* d_in, const int* in_sizes, int n_in,
                              void* d_out, int out_size)
{
    const float* x_in  = (const float*)d_in[0];
    const int*   ei    = (const int*)d_in[1];
    const int*   batch = (const int*)d_in[2];
    const float* attW[3]  = {(const float*)d_in[3],  (const float*)d_in[9],  (const float*)d_in[15]};
    const float* asrc[3]  = {(const float*)d_in[4],  (const float*)d_in[10], (const float*)d_in[16]};
    const float* adst[3]  = {(const float*)d_in[5],  (const float*)d_in[11], (const float*)d_in[17]};
    const float* attb[3]  = {(const float*)d_in[6],  (const float*)d_in[12], (const float*)d_in[18]};
    const float* linW[3]  = {(const float*)d_in[7],  (const float*)d_in[13], (const float*)d_in[19]};
    const float* linb[3]  = {(const float*)d_in[8],  (const float*)d_in[14], (const float*)d_in[20]};
    const float* line1W = (const float*)d_in[21];
    const float* line1b = (const float*)d_in[22];
    const float* line2W = (const float*)d_in[23];
    const float* line2b = (const float*)d_in[24];
    float* out = (float*)d_out;

    static float*  fbuf = nullptr;
    static __half* hbuf = nullptr;
    static int*    ibuf = nullptr;
    if (!fbuf) {
        cudaGetSymbolAddress((void**)&fbuf, g_fbuf);
        cudaGetSymbolAddress((void**)&hbuf, g_hbuf);
        cudaGetSymbolAddress((void**)&ibuf, g_ibuf);
    }

    float* bh    = fbuf + OFF_H;
    float* bx    = fbuf + OFF_X;
    float* bals  = fbuf + OFF_ALS;
    float* bald  = fbuf + OFF_ALD;
    float* bpool = fbuf + OFF_POOL;
    float* bdense= fbuf + OFF_DENSE;
    __half* xh     = hbuf + HOFF_XH;
    __half* attWh[3] = {hbuf + HOFF_ATTW0, hbuf + HOFF_ATTW1, hbuf + HOFF_ATTW2};
    __half* linWh[3] = {hbuf + HOFF_LINW0, hbuf + HOFF_LINW1, hbuf + HOFF_LINW2};
    __half* l1Wh   = hbuf + HOFF_L1W;
    __half* bgath  = hbuf + HOFF_BGAT;
    __half* bxh    = hbuf + HOFF_BXH;
    __half* bpoolh = hbuf + HOFF_BPOOL;
    int* deg    = ibuf + IOFF_DEG;
    int* rows   = ibuf + IOFF_ROWS;
    int* wp     = ibuf + IOFF_WP;
    int* csr    = ibuf + IOFF_CSR;
    int* gstart = ibuf + IOFF_GSTART;

    int mtiles = (NN + 127) / 128;

    // launches 0..2
    {
        int n = GG * 512;
        k_init<<<(n + 255) / 256, 256>>>(deg, bpool);
        k_count<<<(EE + 255) / 256, 256>>>(ei, deg);
        k_cvt8<<<(CVT_TOTAL / 4 + 255) / 256, 256>>>(x_in, attW[0], attW[1], attW[2],
                                                     linW[0], linW[1], linW[2], line1W);
    }

    // launch 3: layer-0 h GEMM (profiled slot)
    {
        dim3 grid(HC / 128, mtiles);
        k_mma<<<grid, 256>>>(xh, attWh[0], nullptr, bh, (__half*)nullptr,
                             NN, F_IN, HC, 0);
    }

    // graph preprocessing (independent of GEMM)
    k_scan<<<1, SCAN_T>>>(deg, rows, wp);
    k_scatter<<<(EE + NN + 255) / 256, 256>>>(ei, wp, csr);
    k_gstart<<<(NN + 255) / 256, 256>>>(batch, gstart);

    // ---- three GAT layers ----
    int fin = F_IN;
    for (int i = 0; i < 3; i++) {
        if (i > 0) {
            dim3 grid(HC / 128, mtiles);
            k_mma<<<grid, 256>>>(bxh, attWh[i], nullptr, bh, (__half*)nullptr,
                                 NN, fin, HC, 0);
        }
        k_al<<<(NN * 32 + 255) / 256, 256>>>(bh, asrc[i], adst[i], bals, bald);
        k_attn<<<(NN * 32 + 255) / 256, 256>>>(bh, bals, bald, attb[i], rows, csr, bgath);
        {
            dim3 grid(EMB / 128, mtiles);
            k_mma<<<grid, 256>>>(bgath, linWh[i], linb[i], bx, bxh, NN, HC, EMB, 1);
        }
        k_pool<<<GG, 256>>>(bx, gstart, bpool);
        fin = EMB;
    }

    // ---- MLP head ----
    k_cvt<<<(GG * 512 + 255) / 256, 256>>>(bpool, bpoolh, GG * 512);
    {
        dim3 grid(DENSE / 128, 1);
        k_mma<<<grid, 256>>>(bpoolh, l1Wh, line1b, bdense, (__half*)nullptr,
                             GG, 2 * EMB, DENSE, 1);
    }
    k_line2<<<GG, 512>>>(bdense, line2W, line2b, out);
}